// round 9
// baseline (speedup 1.0000x reference)
#include <cuda_runtime.h>
#include <cuda_bf16.h>
#include <math.h>
#include <stdint.h>

#define E_DIM 512
#define BLROWS 16384
#define NRR 100
#define NPAD 112                        // 14 n-tiles of 8
#define NORM_TERM 10.82490511970208f    // ln(50257)
#define LOG_NR 4.605170185988092f       // ln(100)
#define MROWS 64                        // rows per CTA
#define ASTR 144                        // smem row stride bytes (72 bf16)
#define APAIR 4608                      // 2 stages x 16 rows x 144B
#define ABYTES 18432                    // 4 pairs
#define BSTAGE 16128                    // 112 rows x 144B
#define NBLK 256

__device__ __align__(16) __nv_bfloat16 g_bn[NPAD * E_DIM];  // bf16 noise table
__device__ float g_part[NBLK];
__device__ int   g_ctr = 0;             // self-resetting (graph-replay safe)

__device__ __forceinline__ uint32_t smem_u32(const void* p) {
    uint32_t a;
    asm("{ .reg .u64 t; cvta.to.shared.u64 t, %1; cvt.u32.u64 %0, t; }" : "=r"(a) : "l"(p));
    return a;
}
__device__ __forceinline__ void cp_async16(uint32_t dst, const void* src) {
    asm volatile("cp.async.cg.shared.global [%0], [%1], 16;" :: "r"(dst), "l"(src));
}
#define MB_INIT(addr, cnt) \
    asm volatile("mbarrier.init.shared.b64 [%0], %1;" :: "r"(addr), "r"(cnt) : "memory")
#define MB_ARRIVE(addr) \
    asm volatile("mbarrier.arrive.shared.b64 _, [%0];" :: "r"(addr) : "memory")
// NOTE: .noinc is load-bearing: without it each arrive increments the expected
// count first (self-cancelling) and the barrier phase never completes -> hang.
#define CPA_MB_ARRIVE(addr) \
    asm volatile("cp.async.mbarrier.arrive.noinc.shared.b64 [%0];" :: "r"(addr) : "memory")
#define MB_WAIT(addr, par) do {                                                     \
    uint32_t _m = (addr), _p = (par), _d;                                           \
    asm volatile("{ .reg .pred p; mbarrier.try_wait.parity.acquire.cta.shared::cta.b64 p, [%1], %2; selp.b32 %0,1,0,p; }" \
        : "=r"(_d) : "r"(_m), "r"(_p) : "memory");                                  \
    if (!_d) {                                                                      \
        asm volatile("{ .reg .pred P1; WL_%=: mbarrier.try_wait.parity.acquire.cta.shared::cta.b64 P1, [%0], %1, 0x989680; @P1 bra.uni WD_%=; bra.uni WL_%=; WD_%=: }" \
            :: "r"(_m), "r"(_p) : "memory");                                        \
    } } while (0)
__device__ __forceinline__ void ldmatrix_x4(uint32_t& r0, uint32_t& r1,
                                            uint32_t& r2, uint32_t& r3, uint32_t addr) {
    asm volatile("ldmatrix.sync.aligned.m8n8.x4.shared.b16 {%0,%1,%2,%3}, [%4];"
                 : "=r"(r0), "=r"(r1), "=r"(r2), "=r"(r3) : "r"(addr));
}
__device__ __forceinline__ void ldmatrix_x2(uint32_t& r0, uint32_t& r1, uint32_t addr) {
    asm volatile("ldmatrix.sync.aligned.m8n8.x2.shared.b16 {%0,%1}, [%2];"
                 : "=r"(r0), "=r"(r1) : "r"(addr));
}
__device__ __forceinline__ void mma16816(float* d, const uint32_t* a,
                                         uint32_t b0, uint32_t b1) {
    asm volatile("mma.sync.aligned.m16n8k16.row.col.f32.bf16.bf16.f32 "
                 "{%0,%1,%2,%3}, {%4,%5,%6,%7}, {%8,%9}, {%0,%1,%2,%3};"
                 : "+f"(d[0]), "+f"(d[1]), "+f"(d[2]), "+f"(d[3])
                 : "r"(a[0]), "r"(a[1]), "r"(a[2]), "r"(a[3]), "r"(b0), "r"(b1));
}
__device__ __forceinline__ float softplus_exact(float x) {
    return fmaxf(x, 0.0f) + log1pf(expf(-fabsf(x)));
}
__device__ __forceinline__ uint2 cvt_bf16x4(float4 v) {
    __nv_bfloat162 p0 = __float22bfloat162_rn(make_float2(v.x, v.y));
    __nv_bfloat162 p1 = __float22bfloat162_rn(make_float2(v.z, v.w));
    uint2 r;
    r.x = *reinterpret_cast<uint32_t*>(&p0);
    r.y = *reinterpret_cast<uint32_t*>(&p1);
    return r;
}

// ---------------------------------------------------------------------------
__global__ void prep_kernel(const float* __restrict__ emb,
                            const int* __restrict__ nidx) {
    int idx = blockIdx.x * blockDim.x + threadIdx.x;
    if (idx >= NPAD * 128) return;
    int n = idx >> 7, q = idx & 127;
    float4 v = make_float4(0.f, 0.f, 0.f, 0.f);
    if (n < NRR) v = *(const float4*)(emb + (size_t)nidx[n] * E_DIM + q * 4);
    *(uint2*)((char*)g_bn + (size_t)n * 1024 + q * 8) = cvt_bf16x4(v);
}

// ---------------------------------------------------------------------------
// 64-row CTAs, 256 thr, 2/SM. Pair {w, w+4} owns 16-row slab (pair-named-bar);
// B: 4-stage cp.async ring with fill/free mbarriers (1 chunk drift tolerance).
// NO CTA-wide barrier in the main loop.
// ---------------------------------------------------------------------------
__global__ void __launch_bounds__(256, 2)
mega_kernel(const float* __restrict__ inp,
            const float* __restrict__ emb,
            const float* __restrict__ bias,
            const float* __restrict__ lpn,
            const int*   __restrict__ tgt,
            const int*   __restrict__ nidx,
            float* __restrict__ out) {
    extern __shared__ char dsm[];
    __shared__ float cs[NPAD];
    __shared__ int   s_t[MROWS];
    __shared__ float s_xc[MROWS];
    __shared__ float s_tp[4 * MROWS];
    __shared__ float s_red[2][MROWS];
    __shared__ float s_fin[MROWS];
    __shared__ int   s_flag;
    __shared__ __align__(8) unsigned long long mb_fill[4], mb_free[4];

    const int tid = threadIdx.x;
    const int lane = tid & 31;
    const int warp = tid >> 5;
    const int p = warp & 3;            // pair id (slab)
    const int h = warp >> 2;           // half within pair; also ngrp
    const int row0 = blockIdx.x * MROWS;

    const uint32_t db = smem_u32(dsm);
    const uint32_t abase = (db + 1023u) & ~1023u;
    const uint32_t bbase = abase + ABYTES;
    char* ap = dsm + (abase - db);

    if (tid < NPAD) {
        int nv = (tid < NRR) ? nidx[tid] : -1;
        cs[tid] = (tid < NRR) ? (bias[nv] - NORM_TERM - lpn[nv] - LOG_NR) : -1e30f;
    }
    if (tid >= 128 && tid < 128 + MROWS) {
        int r = tid - 128;
        int t = tgt[row0 + r];
        s_t[r] = t;
        s_xc[r] = bias[t] - NORM_TERM - lpn[t] - LOG_NR;
    }
    if (tid < 4) MB_INIT(smem_u32(&mb_fill[tid]), 256);
    else if (tid < 8) MB_INIT(smem_u32(&mb_free[tid - 4]), 256);
    __syncthreads();

    uint32_t mf[4], mr[4];
#pragma unroll
    for (int s = 0; s < 4; s++) {
        mf[s] = smem_u32(&mb_fill[s]);
        mr[s] = smem_u32(&mb_free[s]);
    }

    // ---------------- A loader (pair-private) ----------------
    const int r16 = lane & 15;                 // row within slab
    const int ks = h * 2 + (lane >> 4);        // k quarter (16 floats)
    const int cr = p * 16 + r16;               // CTA row
    const float* ipt = inp + (size_t)(row0 + cr) * E_DIM + ks * 16;
    const float* ept = emb + (size_t)s_t[cr] * E_DIM + ks * 16;
    const uint32_t asts = (uint32_t)p * APAIR + r16 * ASTR + ks * 32;

    // B cp.async slots: 896 16B ops over 256 threads
    uint32_t bdst[4], bsrc[4];
    int bok[4];
#pragma unroll
    for (int i = 0; i < 4; i++) {
        int idx = tid + 256 * i;
        bok[i] = (idx < NPAD * 8);
        int n = idx >> 3, sl = idx & 7;
        bdst[i] = (uint32_t)n * ASTR + sl * 16;
        bsrc[i] = (uint32_t)n * 1024 + sl * 16;
    }
    const char* bn = (const char*)g_bn;

    // MMA addressing (proven mapping)
    const uint32_t a_w = abase + (uint32_t)p * APAIR + (lane & 15) * ASTR + ((lane >> 4) << 4);
    const uint32_t b_w = bbase + (uint32_t)(h * 56 + (lane & 7) + ((lane >> 4) << 3)) * ASTR
                       + (((lane >> 3) & 1) << 4);
    const uint32_t b2_w = bbase + (uint32_t)(h * 56 + 48 + (lane & 7)) * ASTR
                        + (((lane >> 3) & 1) << 4);

    float acc[7][4];
#pragma unroll
    for (int n = 0; n < 7; n++)
#pragma unroll
        for (int j = 0; j < 4; j++) acc[n][j] = 0.f;
    float tacc = 0.f;

    // ---------------- prologue ----------------
    float4 va[4], ve[4];
#pragma unroll
    for (int j = 0; j < 4; j++) {
        va[j] = *(const float4*)(ipt + j * 4);
        ve[j] = *(const float4*)(ept + j * 4);
    }
#pragma unroll
    for (int s = 0; s < 2; s++) {      // B(0), B(1)
        uint32_t bs = bbase + s * BSTAGE;
#pragma unroll
        for (int i = 0; i < 4; i++)
            if (bok[i]) cp_async16(bs + bdst[i], bn + bsrc[i] + s * 128);
        CPA_MB_ARRIVE(mf[s]);
    }

    // ---------------- main loop: 8 chunks, no CTA barrier ----------------
#pragma unroll
    for (int c = 0; c < 8; c++) {
        if (c >= 1) MB_ARRIVE(mr[(c - 1) & 3]);   // B stage (c-1) reads done
        // target-dot + convert + STS A(c) into pair stage c&1
        {
            char* adst = ap + asts + (c & 1) * 2304;
#pragma unroll
            for (int j = 0; j < 4; j++) {
                tacc += va[j].x * ve[j].x + va[j].y * ve[j].y
                      + va[j].z * ve[j].z + va[j].w * ve[j].w;
                *(uint2*)(adst + j * 8) = cvt_bf16x4(va[j]);
            }
        }
        if (c < 7) {                   // LDG chunk c+1 (1-iter cover, pair-local)
            const int ko = (c + 1) * 64;
#pragma unroll
            for (int j = 0; j < 4; j++) {
                va[j] = *(const float4*)(ipt + ko + j * 4);
                ve[j] = *(const float4*)(ept + ko + j * 4);
            }
        }
        if (c < 6) {                   // cp.async B(c+2)
            if (c >= 2) MB_WAIT(mr[(c + 2) & 3], 0);
            uint32_t bs = bbase + ((c + 2) & 3) * BSTAGE;
            const char* src = bn + (c + 2) * 128;
#pragma unroll
            for (int i = 0; i < 4; i++)
                if (bok[i]) cp_async16(bs + bdst[i], src + bsrc[i]);
            CPA_MB_ARRIVE(mf[(c + 2) & 3]);
        }
        asm volatile("bar.sync %0, 64;" :: "r"(p + 1) : "memory");   // pair: A(c) visible
        MB_WAIT(mf[c & 3], c >> 2);                                   // B(c) ready
        // MMA chunk c: A stage c&1, B stage c&3
        {
            const uint32_t ab = a_w + (c & 1) * 2304;
            const uint32_t bb = b_w + (c & 3) * BSTAGE;
            const uint32_t bb2 = b2_w + (c & 3) * BSTAGE;
#pragma unroll
            for (int k0 = 0; k0 < 4; k0++) {
                uint32_t a[4];
                ldmatrix_x4(a[0], a[1], a[2], a[3], ab + k0 * 32);
#pragma unroll
                for (int q = 0; q < 3; q++) {
                    uint32_t b0, b1, b2, b3;
                    ldmatrix_x4(b0, b1, b2, b3, bb + q * (16 * ASTR) + k0 * 32);
                    mma16816(acc[q * 2], a, b0, b1);
                    mma16816(acc[q * 2 + 1], a, b2, b3);
                }
                uint32_t b0, b1;
                ldmatrix_x2(b0, b1, bb2 + k0 * 32);
                mma16816(acc[6], a, b0, b1);
            }
        }
    }

    __syncthreads();
    s_tp[ks * MROWS + cr] = tacc;      // target-dot partial (k quarter)

    // --- softplus epilogue (product trick; noise x <= -1.8 always) ---
    {
        const int g = lane >> 2;
        const int tq = lane & 3;
        const int m0 = p * 16;
        float plo = 1.f, phi = 1.f;
#pragma unroll
        for (int nt = 0; nt < 7; nt++) {
            float c0 = cs[(h * 7 + nt) * 8 + 2 * tq];
            float c1 = cs[(h * 7 + nt) * 8 + 2 * tq + 1];
            plo *= (1.f + __expf(acc[nt][0] + c0));
            plo *= (1.f + __expf(acc[nt][1] + c1));
            phi *= (1.f + __expf(acc[nt][2] + c0));
            phi *= (1.f + __expf(acc[nt][3] + c1));
        }
        float slo = __logf(plo);
        float shi = __logf(phi);
        slo += __shfl_xor_sync(0xFFFFFFFFu, slo, 1);
        slo += __shfl_xor_sync(0xFFFFFFFFu, slo, 2);
        shi += __shfl_xor_sync(0xFFFFFFFFu, shi, 1);
        shi += __shfl_xor_sync(0xFFFFFFFFu, shi, 2);
        if (tq == 0) {
            s_red[h][m0 + g] = slo;
            s_red[h][m0 + g + 8] = shi;
        }
    }
    __syncthreads();

    // --- per-row combine (+ target slot), block + grid reduce ---
    if (tid < MROWS) {
        float td = s_tp[tid] + s_tp[MROWS + tid] + s_tp[2 * MROWS + tid] + s_tp[3 * MROWS + tid];
        float x0 = td + s_xc[tid];
        s_fin[tid] = s_red[0][tid] + s_red[1][tid] + softplus_exact(x0) - x0;
    }
    __syncthreads();
    if (tid < 32) {
        float s = s_fin[tid] + s_fin[tid + 32];
        s += __shfl_xor_sync(0xFFFFFFFFu, s, 16);
        s += __shfl_xor_sync(0xFFFFFFFFu, s, 8);
        s += __shfl_xor_sync(0xFFFFFFFFu, s, 4);
        s += __shfl_xor_sync(0xFFFFFFFFu, s, 2);
        s += __shfl_xor_sync(0xFFFFFFFFu, s, 1);
        if (lane == 0) {
            g_part[blockIdx.x] = s;
            __threadfence();
            int old = atomicAdd(&g_ctr, 1);
            s_flag = (old == NBLK - 1);
        }
        __syncwarp();
        if (s_flag) {
            __threadfence();
            float t = 0.f;
#pragma unroll
            for (int k = 0; k < NBLK / 32; k++)
                t += *((volatile float*)&g_part[lane + 32 * k]);
            t += __shfl_xor_sync(0xFFFFFFFFu, t, 16);
            t += __shfl_xor_sync(0xFFFFFFFFu, t, 8);
            t += __shfl_xor_sync(0xFFFFFFFFu, t, 4);
            t += __shfl_xor_sync(0xFFFFFFFFu, t, 2);
            t += __shfl_xor_sync(0xFFFFFFFFu, t, 1);
            if (lane == 0) {
                out[0] = t * (1.0f / (float)BLROWS);
                g_ctr = 0;
            }
        }
    }
}

// ---------------------------------------------------------------------------
extern "C" void kernel_launch(void* const* d_in, const int* in_sizes, int n_in,
                              void* d_out, int out_size) {
    const float* inp  = (const float*)d_in[0];
    const float* emb  = (const float*)d_in[1];
    const float* bias = (const float*)d_in[2];
    const float* lpn  = (const float*)d_in[3];
    const int*   tgt  = (const int*)  d_in[4];
    const int*   nidx = (const int*)  d_in[5];
    float* out = (float*)d_out;

    const int DSM = 1024 + ABYTES + 4 * BSTAGE;   // 83968 B per CTA
    cudaFuncSetAttribute(mega_kernel, cudaFuncAttributeMaxDynamicSharedMemorySize, DSM);

    prep_kernel<<<(NPAD * 128 + 255) / 256, 256>>>(emb, nidx);
    mega_kernel<<<NBLK, 256, DSM>>>(inp, emb, bias, lpn, tgt, nidx, out);
}

// round 10
// speedup vs baseline: 1.6829x; 1.6829x over previous
#include <cuda_runtime.h>
#include <cuda_bf16.h>
#include <math.h>
#include <stdint.h>

#define E_DIM 512
#define BLROWS 16384
#define NRR 100
#define NPAD 112                        // 14 n-tiles of 8
#define NORM_TERM 10.82490511970208f    // ln(50257)
#define LOG_NR 4.605170185988092f       // ln(100)
#define MROWS 64                        // rows per CTA
#define ASTR 144                        // bf16 tile row stride (72 bf16)
#define ASTAGE (MROWS * ASTR)           // 9216
#define BSTAGE (NPAD * ASTR)            // 16128
#define GSTAGE (MROWS * 256)            // 16384: f32 gather rows (64 x 256B)
#define NBLK 256

__device__ __align__(16) __nv_bfloat16 g_bn[NPAD * E_DIM];  // bf16 noise table
__device__ float g_part[NBLK];
__device__ int   g_ctr = 0;             // self-resetting (graph-replay safe)

__device__ __forceinline__ uint32_t smem_u32(const void* p) {
    uint32_t a;
    asm("{ .reg .u64 t; cvta.to.shared.u64 t, %1; cvt.u32.u64 %0, t; }" : "=r"(a) : "l"(p));
    return a;
}
__device__ __forceinline__ void cp_async16(uint32_t dst, const void* src) {
    asm volatile("cp.async.cg.shared.global [%0], [%1], 16;" :: "r"(dst), "l"(src) : "memory");
}
#define CP_COMMIT() asm volatile("cp.async.commit_group;" ::: "memory")
#define CP_WAIT1()  asm volatile("cp.async.wait_group 1;" ::: "memory")
__device__ __forceinline__ void ldmatrix_x4(uint32_t& r0, uint32_t& r1,
                                            uint32_t& r2, uint32_t& r3, uint32_t addr) {
    asm volatile("ldmatrix.sync.aligned.m8n8.x4.shared.b16 {%0,%1,%2,%3}, [%4];"
                 : "=r"(r0), "=r"(r1), "=r"(r2), "=r"(r3) : "r"(addr));
}
__device__ __forceinline__ void ldmatrix_x2(uint32_t& r0, uint32_t& r1, uint32_t addr) {
    asm volatile("ldmatrix.sync.aligned.m8n8.x2.shared.b16 {%0,%1}, [%2];"
                 : "=r"(r0), "=r"(r1) : "r"(addr));
}
__device__ __forceinline__ void mma16816(float* d, const uint32_t* a,
                                         uint32_t b0, uint32_t b1) {
    asm volatile("mma.sync.aligned.m16n8k16.row.col.f32.bf16.bf16.f32 "
                 "{%0,%1,%2,%3}, {%4,%5,%6,%7}, {%8,%9}, {%0,%1,%2,%3};"
                 : "+f"(d[0]), "+f"(d[1]), "+f"(d[2]), "+f"(d[3])
                 : "r"(a[0]), "r"(a[1]), "r"(a[2]), "r"(a[3]), "r"(b0), "r"(b1));
}
__device__ __forceinline__ float softplus_exact(float x) {
    return fmaxf(x, 0.0f) + log1pf(expf(-fabsf(x)));
}
__device__ __forceinline__ uint2 cvt_bf16x4(float4 v) {
    __nv_bfloat162 p0 = __float22bfloat162_rn(make_float2(v.x, v.y));
    __nv_bfloat162 p1 = __float22bfloat162_rn(make_float2(v.z, v.w));
    uint2 r;
    r.x = *reinterpret_cast<uint32_t*>(&p0);
    r.y = *reinterpret_cast<uint32_t*>(&p1);
    return r;
}

// ---------------------------------------------------------------------------
__global__ void prep_kernel(const float* __restrict__ emb,
                            const int* __restrict__ nidx) {
    int idx = blockIdx.x * blockDim.x + threadIdx.x;
    if (idx >= NPAD * 128) return;
    int n = idx >> 7, q = idx & 127;
    float4 v = make_float4(0.f, 0.f, 0.f, 0.f);
    if (n < NRR) v = *(const float4*)(emb + (size_t)nidx[n] * E_DIM + q * 4);
    *(uint2*)((char*)g_bn + (size_t)n * 1024 + q * 8) = cvt_bf16x4(v);
}

// ---------------------------------------------------------------------------
// 64-row CTAs, 256 thr, 2/SM, one __syncthreads per chunk.
// Gather (emb[target]) via cp.async f32 ring (2 stages, distance 2, zero regs);
// input via register prefetch (depth 2); B via cp.async bf16 ring (3 stages).
// ---------------------------------------------------------------------------
__global__ void __launch_bounds__(256, 2)
mega_kernel(const float* __restrict__ inp,
            const float* __restrict__ emb,
            const float* __restrict__ bias,
            const float* __restrict__ lpn,
            const int*   __restrict__ tgt,
            const int*   __restrict__ nidx,
            float* __restrict__ out) {
    extern __shared__ char dsm[];
    __shared__ float cs[NPAD];
    __shared__ int   s_t[MROWS];
    __shared__ float s_xc[MROWS];
    __shared__ float s_tdot[MROWS];
    __shared__ float s_red[2][MROWS];
    __shared__ float s_fin[MROWS];
    __shared__ int   s_flag;

    const int tid = threadIdx.x;
    const int lane = tid & 31;
    const int row0 = blockIdx.x * MROWS;

    const uint32_t db = smem_u32(dsm);
    const uint32_t abase = (db + 1023u) & ~1023u;
    const uint32_t bbase = abase + 2 * ASTAGE;
    const uint32_t gbase = bbase + 3 * BSTAGE;
    char* ap = dsm + (abase - db);
    char* gp = dsm + (gbase - db);

    if (tid < NPAD) {
        int nv = (tid < NRR) ? nidx[tid] : -1;
        cs[tid] = (tid < NRR) ? (bias[nv] - NORM_TERM - lpn[nv] - LOG_NR) : -1e30f;
    }
    if (tid >= 128 && tid < 128 + MROWS) {
        int r = tid - 128;
        int t = tgt[row0 + r];
        s_t[r] = t;
        s_xc[r] = bias[t] - NORM_TERM - lpn[t] - LOG_NR;
    }
    __syncthreads();

    // ---------------- per-thread layout ----------------
    const int l4 = tid & 15;            // 16B k-slot
    const int rg = tid >> 4;            // 0..15; rows rg+16j
    const float* ipt = inp + (size_t)(row0 + rg) * E_DIM + l4 * 4;
    const uint32_t asts = (uint32_t)rg * ASTR + l4 * 8;

    // gather cp.async: op i covers (row = rg+16i, seg = l4) -> this thread
    // is also the reader of exactly these bytes (no cross-thread visibility needed)
    const char* embB = (const char*)emb;
    uint32_t gsrc[4], gdst[4];
#pragma unroll
    for (int i = 0; i < 4; i++) {
        int row = rg + 16 * i;
        gsrc[i] = (uint32_t)s_t[row] * 2048u + (uint32_t)l4 * 16u;
        gdst[i] = (uint32_t)row * 256u + (uint32_t)l4 * 16u;
    }

    // B cp.async slots: 896 16B ops over 256 threads
    uint32_t bdst[4], bsrc[4];
    int bok[4];
#pragma unroll
    for (int i = 0; i < 4; i++) {
        int idx = tid + 256 * i;
        bok[i] = (idx < NPAD * 8);
        int n = idx >> 3, sl = idx & 7;
        bdst[i] = (uint32_t)n * ASTR + sl * 16;
        bsrc[i] = (uint32_t)n * 1024 + sl * 16;
    }
    const char* bn = (const char*)g_bn;

    // MMA fragment addressing (proven mapping)
    const int m0 = (tid >> 5 & 3) * 16;
    const int ngrp = tid >> 7;
    const uint32_t a_woff = (uint32_t)(m0 + (lane & 15)) * ASTR + ((lane >> 4) << 4);
    const uint32_t b_woff = (uint32_t)(ngrp * 56 + (lane & 7) + ((lane >> 4) << 3)) * ASTR
                          + (((lane >> 3) & 1) << 4);
    const uint32_t b2_woff = (uint32_t)(ngrp * 56 + 48 + (lane & 7)) * ASTR
                           + (((lane >> 3) & 1) << 4);

    float acc[7][4];
#pragma unroll
    for (int n = 0; n < 7; n++)
#pragma unroll
        for (int j = 0; j < 4; j++) acc[n][j] = 0.f;
    float tacc[4] = {0.f, 0.f, 0.f, 0.f};

    // ---------------- prologue ----------------
    float4 va[2][4];
#pragma unroll
    for (int s = 0; s < 2; s++)
#pragma unroll
        for (int j = 0; j < 4; j++)
            va[s][j] = *(const float4*)(ipt + s * 64 + j * (16 * E_DIM));
#pragma unroll
    for (int s = 0; s < 2; s++) {       // groups: {gather(s), B(s)}
        uint32_t gs = gbase + s * GSTAGE;
        uint32_t bs = bbase + s * BSTAGE;
#pragma unroll
        for (int i = 0; i < 4; i++)
            cp_async16(gs + gdst[i], embB + gsrc[i] + s * 256);
#pragma unroll
        for (int i = 0; i < 4; i++)
            if (bok[i]) cp_async16(bs + bdst[i], bn + bsrc[i] + s * 128);
        CP_COMMIT();
    }

    // ---------------- main loop: 8 chunks, ONE sync each ----------------
#pragma unroll
    for (int c = 0; c < 8; c++) {
        const int set = c & 1;
        CP_WAIT1();                     // gather(c), B(c) resident (own ops)
        // dot (LDS f32 gather x va regs) + convert + STS A(c) into stage c&1
        {
            char* adst = ap + set * ASTAGE + asts;
            const char* gsp = gp + set * GSTAGE + rg * 256 + l4 * 16;
#pragma unroll
            for (int j = 0; j < 4; j++) {
                float4 gv = *(const float4*)(gsp + j * (16 * 256));
                tacc[j] += va[set][j].x * gv.x + va[set][j].y * gv.y
                         + va[set][j].z * gv.z + va[set][j].w * gv.w;
                *(uint2*)(adst + j * (16 * ASTR)) = cvt_bf16x4(va[set][j]);
            }
        }
        if (c < 6) {                    // input LDG chunk c+2 (register, 2-iter cover)
            const int ko = (c + 2) * 64;
#pragma unroll
            for (int j = 0; j < 4; j++)
                va[set][j] = *(const float4*)(ipt + ko + j * (16 * E_DIM));
        }
        __syncthreads();                // A(c)/prior B visible; MMA(c-1) done by all
        if (c < 6) {                    // cp.async gather(c+2) + B(c+2)
            uint32_t gs = gbase + set * GSTAGE;              // (c+2)&1 == c&1
            uint32_t bs = bbase + ((c + 2) % 3) * BSTAGE;    // constant-folded
            const char* bsr = bn + (c + 2) * 128;
#pragma unroll
            for (int i = 0; i < 4; i++)
                cp_async16(gs + gdst[i], embB + gsrc[i] + (c + 2) * 256);
#pragma unroll
            for (int i = 0; i < 4; i++)
                if (bok[i]) cp_async16(bs + bdst[i], bsr + bsrc[i]);
        }
        CP_COMMIT();                    // always (keeps group counting uniform)
        // MMA chunk c: A stage c&1, B stage c%3
        {
            const uint32_t ab = abase + set * ASTAGE + a_woff;
            const uint32_t bb = bbase + (c % 3) * BSTAGE + b_woff;
            const uint32_t bb2 = bbase + (c % 3) * BSTAGE + b2_woff;
#pragma unroll
            for (int k0 = 0; k0 < 4; k0++) {
                uint32_t a[4];
                ldmatrix_x4(a[0], a[1], a[2], a[3], ab + k0 * 32);
#pragma unroll
                for (int q = 0; q < 3; q++) {
                    uint32_t b0, b1, b2, b3;
                    ldmatrix_x4(b0, b1, b2, b3, bb + q * (16 * ASTR) + k0 * 32);
                    mma16816(acc[q * 2], a, b0, b1);
                    mma16816(acc[q * 2 + 1], a, b2, b3);
                }
                uint32_t b0, b1;
                ldmatrix_x2(b0, b1, bb2 + k0 * 32);
                mma16816(acc[6], a, b0, b1);
            }
        }
    }

    // --- finish exact target dots (reduce over the 16 k-slot lanes) ---
#pragma unroll
    for (int j = 0; j < 4; j++) {
        float v = tacc[j];
        v += __shfl_xor_sync(0xFFFFFFFFu, v, 8);
        v += __shfl_xor_sync(0xFFFFFFFFu, v, 4);
        v += __shfl_xor_sync(0xFFFFFFFFu, v, 2);
        v += __shfl_xor_sync(0xFFFFFFFFu, v, 1);
        if (l4 == 0) s_tdot[rg + 16 * j] = v;
    }

    // --- softplus epilogue (product trick; noise x <= -1.8 always) ---
    {
        const int g = lane >> 2;
        const int tq = lane & 3;
        float plo = 1.f, phi = 1.f;
#pragma unroll
        for (int nt = 0; nt < 7; nt++) {
            float c0 = cs[(ngrp * 7 + nt) * 8 + 2 * tq];
            float c1 = cs[(ngrp * 7 + nt) * 8 + 2 * tq + 1];
            plo *= (1.f + __expf(acc[nt][0] + c0));
            plo *= (1.f + __expf(acc[nt][1] + c1));
            phi *= (1.f + __expf(acc[nt][2] + c0));
            phi *= (1.f + __expf(acc[nt][3] + c1));
        }
        float slo = __logf(plo);
        float shi = __logf(phi);
        slo += __shfl_xor_sync(0xFFFFFFFFu, slo, 1);
        slo += __shfl_xor_sync(0xFFFFFFFFu, slo, 2);
        shi += __shfl_xor_sync(0xFFFFFFFFu, shi, 1);
        shi += __shfl_xor_sync(0xFFFFFFFFu, shi, 2);
        if (tq == 0) {
            s_red[ngrp][m0 + g] = slo;
            s_red[ngrp][m0 + g + 8] = shi;
        }
    }
    __syncthreads();

    // --- per-row combine (+ target slot), block + grid reduce ---
    if (tid < MROWS) {
        float x0 = s_tdot[tid] + s_xc[tid];
        s_fin[tid] = s_red[0][tid] + s_red[1][tid] + softplus_exact(x0) - x0;
    }
    __syncthreads();
    if (tid < 32) {
        float s = s_fin[tid] + s_fin[tid + 32];
        s += __shfl_xor_sync(0xFFFFFFFFu, s, 16);
        s += __shfl_xor_sync(0xFFFFFFFFu, s, 8);
        s += __shfl_xor_sync(0xFFFFFFFFu, s, 4);
        s += __shfl_xor_sync(0xFFFFFFFFu, s, 2);
        s += __shfl_xor_sync(0xFFFFFFFFu, s, 1);
        if (lane == 0) {
            g_part[blockIdx.x] = s;
            __threadfence();
            int old = atomicAdd(&g_ctr, 1);
            s_flag = (old == NBLK - 1);
        }
        __syncwarp();
        if (s_flag) {
            __threadfence();
            float t = 0.f;
#pragma unroll
            for (int k = 0; k < NBLK / 32; k++)
                t += *((volatile float*)&g_part[lane + 32 * k]);
            t += __shfl_xor_sync(0xFFFFFFFFu, t, 16);
            t += __shfl_xor_sync(0xFFFFFFFFu, t, 8);
            t += __shfl_xor_sync(0xFFFFFFFFu, t, 4);
            t += __shfl_xor_sync(0xFFFFFFFFu, t, 2);
            t += __shfl_xor_sync(0xFFFFFFFFu, t, 1);
            if (lane == 0) {
                out[0] = t * (1.0f / (float)BLROWS);
                g_ctr = 0;
            }
        }
    }
}

// ---------------------------------------------------------------------------
extern "C" void kernel_launch(void* const* d_in, const int* in_sizes, int n_in,
                              void* d_out, int out_size) {
    const float* inp  = (const float*)d_in[0];
    const float* emb  = (const float*)d_in[1];
    const float* bias = (const float*)d_in[2];
    const float* lpn  = (const float*)d_in[3];
    const int*   tgt  = (const int*)  d_in[4];
    const int*   nidx = (const int*)  d_in[5];
    float* out = (float*)d_out;

    const int DSM = 1024 + 2 * ASTAGE + 3 * BSTAGE + 2 * GSTAGE;  // 100608 B
    cudaFuncSetAttribute(mega_kernel, cudaFuncAttributeMaxDynamicSharedMemorySize, DSM);

    prep_kernel<<<(NPAD * 128 + 255) / 256, 256>>>(emb, nidx);
    mega_kernel<<<NBLK, 256, DSM>>>(inp, emb, bias, lpn, tgt, nidx, out);
}